// round 10
// baseline (speedup 1.0000x reference)
#include <cuda_runtime.h>

#define N_NODES 40000
#define N_EDGES 640000
#define NPAD    40960   // N_NODES padded to 40*1024 for the scan

// Scratch (allocation-free rule: __device__ globals)
__device__ float g_sv[N_NODES * 128];    // lin1 out, quad: [node][lane]=(s,vx,vy,vz)
__device__ float g_acc[N_NODES * 256];   // aggregation, quad-interleaved
__device__ int   g_hist[NPAD];           // per-dst edge counts
__device__ int   g_start[NPAD];          // exclusive scan (within 1024-block)
__device__ int   g_cursor[NPAD];         // scatter cursors
__device__ int   g_bsum[40];             // per-scan-block totals
__device__ int   g_bscan[40];            // scanned block totals
__device__ int   g_perm[N_EDGES];        // dst-sorted edge permutation

__device__ __forceinline__ float silu_n(float x) {
    return (x / (1.0f + __expf(-x))) * 1.6791767923989418f;
}

// ---- f32x2 packed helpers (Blackwell) -------------------------------------
__device__ __forceinline__ unsigned long long pk(float a, float b) {
    unsigned long long r;
    asm("mov.b64 %0, {%1,%2};" : "=l"(r) : "f"(a), "f"(b));
    return r;
}
__device__ __forceinline__ void fma2(unsigned long long& d,
                                     unsigned long long a, unsigned long long b) {
    asm("fma.rn.f32x2 %0, %1, %2, %0;" : "+l"(d) : "l"(a), "l"(b));
}
__device__ __forceinline__ float2 unpk(unsigned long long v) {
    float2 r;
    asm("mov.b64 {%0,%1}, %2;" : "=f"(r.x), "=f"(r.y) : "l"(v));
    return r;
}
__device__ __forceinline__ void red4(float* p, float a, float b, float c, float d) {
    asm volatile("red.global.add.v4.f32 [%0], {%1,%2,%3,%4};"
                 :: "l"(p), "f"(a), "f"(b), "f"(c), "f"(d) : "memory");
}

// ---------------------------------------------------------------------------
// Binning pipeline: dst-sorted edge permutation
// ---------------------------------------------------------------------------
__global__ void prep_zero_kernel() {
    int i = blockIdx.x * blockDim.x + threadIdx.x;
    if (i < NPAD) { g_hist[i] = 0; g_cursor[i] = 0; }
}

__global__ void hist_kernel(const int* __restrict__ edst) {
    int e = blockIdx.x * blockDim.x + threadIdx.x;
    if (e < N_EDGES) atomicAdd(&g_hist[edst[e]], 1);
}

// 40 blocks x 1024: per-block exclusive scan + block totals
__global__ void scan1_kernel() {
    __shared__ int sh[1024];
    int tid = threadIdx.x;
    int i = blockIdx.x * 1024 + tid;
    int v = g_hist[i];
    sh[tid] = v;
    __syncthreads();
#pragma unroll
    for (int off = 1; off < 1024; off <<= 1) {
        int t = (tid >= off) ? sh[tid - off] : 0;
        __syncthreads();
        sh[tid] += t;
        __syncthreads();
    }
    g_start[i] = sh[tid] - v;   // exclusive within block
    if (tid == 1023) g_bsum[blockIdx.x] = sh[1023];
}

__global__ void scan2_kernel() {
    if (threadIdx.x == 0) {
        int s = 0;
#pragma unroll
        for (int b = 0; b < 40; b++) { g_bscan[b] = s; s += g_bsum[b]; }
    }
}

__global__ void scatter_kernel(const int* __restrict__ edst) {
    int e = blockIdx.x * blockDim.x + threadIdx.x;
    if (e < N_EDGES) {
        int d = edst[e];
        int pos = g_start[d] + g_bscan[d >> 10] + atomicAdd(&g_cursor[d], 1);
        g_perm[pos] = e;
    }
}

// ---------------------------------------------------------------------------
// K1: lin1 (+ zero g_acc) — quad output layout
// ---------------------------------------------------------------------------
__global__ void lin1_kernel(const float* __restrict__ ni,
                            const float* __restrict__ w1s,
                            const float* __restrict__ w1v) {
    __shared__ float sWs[1024], sWv[1024];
    __shared__ float srow[8][128];
    int tid = threadIdx.x;
    {
        float4 z = make_float4(0.f, 0.f, 0.f, 0.f);
        size_t base = (size_t)blockIdx.x * 512;
        ((float4*)g_acc)[base + tid]       = z;
        ((float4*)g_acc)[base + 256 + tid] = z;
    }
    const float sc = 0.17677669529663687f;  // 1/sqrt(32)
    for (int i = tid; i < 1024; i += 256) { sWs[i] = w1s[i] * sc; sWv[i] = w1v[i] * sc; }
    __syncthreads();

    int warp = tid >> 5, lane = tid & 31;
    int node = blockIdx.x * 8 + warp;
    ((float4*)srow[warp])[lane] = ((const float4*)(ni + (size_t)node * 128))[lane];
    __syncwarp();

    float s = 0.f, v0 = 0.f, v1 = 0.f, v2 = 0.f;
#pragma unroll
    for (int u = 0; u < 32; u++) {
        float su = srow[warp][u];
        float a0 = srow[warp][32 + u * 3 + 0];
        float a1 = srow[warp][32 + u * 3 + 1];
        float a2 = srow[warp][32 + u * 3 + 2];
        float ws = sWs[u * 32 + lane];
        float wv = sWv[u * 32 + lane];
        s  = fmaf(su, ws, s);
        v0 = fmaf(a0, wv, v0);
        v1 = fmaf(a1, wv, v1);
        v2 = fmaf(a2, wv, v2);
    }
    ((float4*)(g_sv + (size_t)node * 128))[lane] = make_float4(s, v0, v1, v2);
}

// ---------------------------------------------------------------------------
// K2: edge kernel — R2 Phase A/B; edges walked in dst-sorted order (perm),
// Phase C accumulates in registers per dst-run, REDs only on dst change.
// ---------------------------------------------------------------------------
#define EPW 8
__global__ void __launch_bounds__(128, 4)
edge_kernel(const int*    __restrict__ esrc,
            const int*    __restrict__ edst,
            const float4* __restrict__ eattr,
            const float4* __restrict__ escal,
            const float*  __restrict__ fw1,
            const float*  __restrict__ fw2) {
    __shared__ float sF1[512];
    __shared__ float sF2p[8192];
    __shared__ float h_sh[4][64 * EPW];
    int tid = threadIdx.x;
    for (int i = tid; i < 512; i += 128) sF1[i] = fw1[i] * 0.3535533905932738f;
    for (int i = tid; i < 8192; i += 128) {
        int j = i >> 7;
        int r = i & 127;
        int l = r >> 2, k = r & 3;
        sF2p[i] = fw2[j * 128 + k * 32 + l] * 0.125f;
    }
    __syncthreads();

    int lane = tid & 31, warp = tid >> 5;
    float* hs = h_sh[warp];
    int wg = blockIdx.x * 4 + warp;
    int nw = gridDim.x * 4;
    const int ngroups = N_EDGES / EPW;

    for (int g = wg; g < ngroups; g += nw) {
        int e0 = g * EPW;
        int src[EPW], dst[EPW];
        float es[EPW], evx[EPW], evy[EPW], evz[EPW];
        float h0[EPW], h1[EPW];

        // Phase A: permuted (dst-sorted) edge loads + first MLP layer
#pragma unroll
        for (int e = 0; e < EPW; e++) {
            int ed = g_perm[e0 + e];     // uniform load
            src[e] = esrc[ed];
            dst[e] = edst[ed];
            float4 ea = eattr[ed];
            es[e] = ea.x; evx[e] = ea.y; evy[e] = ea.z; evz[e] = ea.w;
            float4 sA = escal[ed * 2 + 0];
            float4 sB = escal[ed * 2 + 1];
            float sc8[8] = {sA.x, sA.y, sA.z, sA.w, sB.x, sB.y, sB.z, sB.w};
            float a0 = 0.f, a1 = 0.f;
#pragma unroll
            for (int i = 0; i < 8; i++) {
                a0 = fmaf(sc8[i], sF1[i * 64 + lane],      a0);
                a1 = fmaf(sc8[i], sF1[i * 64 + 32 + lane], a1);
            }
            h0[e] = silu_n(a0);
            h1[e] = silu_n(a1);
        }
        __syncwarp();
        ((float4*)hs)[lane * 2 + 0]      = make_float4(h0[0], h0[1], h0[2], h0[3]);
        ((float4*)hs)[lane * 2 + 1]      = make_float4(h0[4], h0[5], h0[6], h0[7]);
        ((float4*)hs)[64 + lane * 2 + 0] = make_float4(h1[0], h1[1], h1[2], h1[3]);
        ((float4*)hs)[64 + lane * 2 + 1] = make_float4(h1[4], h1[5], h1[6], h1[7]);
        __syncwarp();

        // Phase B: layer 2 with packed f32x2 FMA (R2-exact)
        unsigned long long w01[EPW], w23[EPW];
#pragma unroll
        for (int e = 0; e < EPW; e++) { w01[e] = 0ull; w23[e] = 0ull; }
#pragma unroll 8
        for (int j = 0; j < 64; j++) {
            float4 bw = ((const float4*)sF2p)[j * 32 + lane];
            unsigned long long b01 = pk(bw.x, bw.y);
            unsigned long long b23 = pk(bw.z, bw.w);
            float4 hA = ((const float4*)hs)[j * 2 + 0];
            float4 hB = ((const float4*)hs)[j * 2 + 1];
            float hv[EPW] = {hA.x, hA.y, hA.z, hA.w, hB.x, hB.y, hB.z, hB.w};
#pragma unroll
            for (int e = 0; e < EPW; e++) {
                unsigned long long hh = pk(hv[e], hv[e]);
                fma2(w01[e], hh, b01);
                fma2(w23[e], hh, b23);
            }
        }

        // Phase C: gather + tensor product; register accumulation per dst-run,
        // RED flush only when dst changes (edges are dst-sorted).
        int cur = dst[0];
        float A0 = 0.f, A1 = 0.f, A2 = 0.f, A3 = 0.f;
        float B0 = 0.f, B1 = 0.f, B2 = 0.f, B3 = 0.f;
#pragma unroll
        for (int e = 0; e < EPW; e++) {
            if (dst[e] != cur) {   // warp-uniform branch
                float* ar = g_acc + (size_t)cur * 256;
                red4(ar + lane * 4,       A0, A1, A2, A3);
                red4(ar + 128 + lane * 4, B0, B1, B2, B3);
                A0 = A1 = A2 = A3 = B0 = B1 = B2 = B3 = 0.f;
                cur = dst[e];
            }
            float4 q = ((const float4*)(g_sv + (size_t)src[e] * 128))[lane];
            float se = q.x, vx = q.y, vy = q.z, vz = q.w;
            float2 a01 = unpk(w01[e]);  // (w0, w1)
            float2 a23 = unpk(w23[e]);  // (w2, w3)
            float dotv = fmaf(vx, evx[e], fmaf(vy, evy[e], vz * evz[e]));
            float ms0 = a01.x * se * es[e];
            float ms1 = a23.y * dotv * 0.5773502691896258f;  // 1/sqrt(3)
            float aa  = a01.y * se;
            float bb  = a23.x * es[e];
            A0 += ms0;       A1 += aa * evx[e]; A2 += aa * evy[e]; A3 += aa * evz[e];
            B0 += ms1;       B1 += bb * vx;     B2 += bb * vy;     B3 += bb * vz;
        }
        {
            float* ar = g_acc + (size_t)cur * 256;
            red4(ar + lane * 4,       A0, A1, A2, A3);
            red4(ar + 128 + lane * 4, B0, B1, B2, B3);
        }
    }
}

// ---------------------------------------------------------------------------
// K3: lin2 — TRUE R2 version (measured 51us)
// ---------------------------------------------------------------------------
__global__ void lin2_kernel(const float* __restrict__ w2s,
                            const float* __restrict__ w2v,
                            float* __restrict__ out) {
    __shared__ float sW[4096];
    __shared__ float srow[8][256];
    int tid = threadIdx.x;
    const float sc = 0.03125f;
    for (int i = tid; i < 2048; i += 256) {
        sW[i * 2 + 0] = w2s[i] * sc;
        sW[i * 2 + 1] = w2v[i] * sc;
    }
    __syncthreads();

    int warp = tid >> 5, lane = tid & 31;
    int node = blockIdx.x * 8 + warp;

    const float4* ar = (const float4*)(g_acc + (size_t)node * 256);
    ((float4*)srow[warp])[lane]      = ar[lane];
    ((float4*)srow[warp])[lane + 32] = ar[lane + 32];
    __syncwarp();

    unsigned long long acc0 = 0ull, acc1 = 0ull;
#pragma unroll 8
    for (int u = 0; u < 64; u++) {
        float4 q = ((const float4*)srow[warp])[u];
        float2 wsv = ((const float2*)sW)[u * 32 + lane];
        fma2(acc0, pk(q.x, q.y), pk(wsv.x, wsv.y));
        fma2(acc1, pk(q.z, q.w), pk(wsv.y, wsv.y));
    }
    float2 r0 = unpk(acc0), r1 = unpk(acc1);
    float* o = out + (size_t)node * 128;
    o[lane] = r0.x;
    o[32 + lane * 3 + 0] = r0.y;
    o[32 + lane * 3 + 1] = r1.x;
    o[32 + lane * 3 + 2] = r1.y;
}

// ---------------------------------------------------------------------------
extern "C" void kernel_launch(void* const* d_in, const int* in_sizes, int n_in,
                              void* d_out, int out_size) {
    const float* node_input = (const float*)d_in[0];
    const int*   esrc  = (const int*)d_in[2];
    const int*   edst  = (const int*)d_in[3];
    const float* eattr = (const float*)d_in[4];
    const float* escal = (const float*)d_in[5];
    const float* w1s   = (const float*)d_in[6];
    const float* w1v   = (const float*)d_in[7];
    const float* fw1   = (const float*)d_in[8];
    const float* fw2   = (const float*)d_in[9];
    const float* w2s   = (const float*)d_in[10];
    const float* w2v   = (const float*)d_in[11];
    float* out = (float*)d_out;

    // binning pipeline (dst-sorted permutation)
    prep_zero_kernel<<<(NPAD + 255) / 256, 256>>>();
    hist_kernel<<<(N_EDGES + 255) / 256, 256>>>(edst);
    scan1_kernel<<<40, 1024>>>();
    scan2_kernel<<<1, 32>>>();
    scatter_kernel<<<(N_EDGES + 255) / 256, 256>>>(edst);

    lin1_kernel<<<N_NODES / 8, 256>>>(node_input, w1s, w1v);
    edge_kernel<<<592, 128>>>(esrc, edst, (const float4*)eattr,
                              (const float4*)escal, fw1, fw2);
    lin2_kernel<<<N_NODES / 8, 256>>>(w2s, w2v, out);
}

// round 11
// speedup vs baseline: 1.0394x; 1.0394x over previous
#include <cuda_runtime.h>

#define N_NODES 40000
#define N_EDGES 640000
#define NPAD    40960   // N_NODES padded to 40*1024 for the scan

// Scratch (allocation-free rule: __device__ globals)
__device__ float g_sv[N_NODES * 128];    // lin1 out, quad: [node][lane]=(s,vx,vy,vz)
__device__ float g_acc[N_NODES * 256];   // aggregation, quad-interleaved
__device__ int   g_hist[NPAD];           // per-dst edge counts
__device__ int   g_start[NPAD];          // exclusive scan (within 1024-block)
__device__ int   g_cursor[NPAD];         // scatter cursors
__device__ int   g_bsum[40];             // per-scan-block totals
__device__ int   g_bscan[40];            // scanned block totals
// SORTED edge data (dst-ascending)
__device__ int2   g_ssd[N_EDGES];        // (src, dst)
__device__ float4 g_sea[N_EDGES];        // edge_attr
__device__ float4 g_ses[N_EDGES * 2];    // edge_scalars

__device__ __forceinline__ float silu_n(float x) {
    return (x / (1.0f + __expf(-x))) * 1.6791767923989418f;
}

// ---- f32x2 packed helpers (Blackwell) -------------------------------------
__device__ __forceinline__ unsigned long long pk(float a, float b) {
    unsigned long long r;
    asm("mov.b64 %0, {%1,%2};" : "=l"(r) : "f"(a), "f"(b));
    return r;
}
__device__ __forceinline__ void fma2(unsigned long long& d,
                                     unsigned long long a, unsigned long long b) {
    asm("fma.rn.f32x2 %0, %1, %2, %0;" : "+l"(d) : "l"(a), "l"(b));
}
__device__ __forceinline__ float2 unpk(unsigned long long v) {
    float2 r;
    asm("mov.b64 {%0,%1}, %2;" : "=f"(r.x), "=f"(r.y) : "l"(v));
    return r;
}
__device__ __forceinline__ void red4(float* p, float a, float b, float c, float d) {
    asm volatile("red.global.add.v4.f32 [%0], {%1,%2,%3,%4};"
                 :: "l"(p), "f"(a), "f"(b), "f"(c), "f"(d) : "memory");
}

// ---------------------------------------------------------------------------
// Binning pipeline: dst-sorted materialized edge arrays
// ---------------------------------------------------------------------------
__global__ void prep_zero_kernel() {
    int i = blockIdx.x * blockDim.x + threadIdx.x;
    if (i < NPAD) { g_hist[i] = 0; g_cursor[i] = 0; }
}

__global__ void hist_kernel(const int* __restrict__ edst) {
    int e = blockIdx.x * blockDim.x + threadIdx.x;
    if (e < N_EDGES) atomicAdd(&g_hist[edst[e]], 1);
}

// 40 blocks x 1024: per-block exclusive scan + block totals
__global__ void scan1_kernel() {
    __shared__ int sh[1024];
    int tid = threadIdx.x;
    int i = blockIdx.x * 1024 + tid;
    int v = g_hist[i];
    sh[tid] = v;
    __syncthreads();
#pragma unroll
    for (int off = 1; off < 1024; off <<= 1) {
        int t = (tid >= off) ? sh[tid - off] : 0;
        __syncthreads();
        sh[tid] += t;
        __syncthreads();
    }
    g_start[i] = sh[tid] - v;   // exclusive within block
    if (tid == 1023) g_bsum[blockIdx.x] = sh[1023];
}

__global__ void scan2_kernel() {
    if (threadIdx.x == 0) {
        int s = 0;
#pragma unroll
        for (int b = 0; b < 40; b++) { g_bscan[b] = s; s += g_bsum[b]; }
    }
}

// scatter: write SORTED copies of all edge data
__global__ void scatter_kernel(const int*    __restrict__ esrc,
                               const int*    __restrict__ edst,
                               const float4* __restrict__ eattr,
                               const float4* __restrict__ escal) {
    int e = blockIdx.x * blockDim.x + threadIdx.x;
    if (e < N_EDGES) {
        int d = edst[e];
        int pos = g_start[d] + g_bscan[d >> 10] + atomicAdd(&g_cursor[d], 1);
        g_ssd[pos] = make_int2(esrc[e], d);
        g_sea[pos] = eattr[e];
        g_ses[pos * 2 + 0] = escal[e * 2 + 0];
        g_ses[pos * 2 + 1] = escal[e * 2 + 1];
    }
}

// ---------------------------------------------------------------------------
// K1: lin1 (+ zero g_acc) — quad output layout
// ---------------------------------------------------------------------------
__global__ void lin1_kernel(const float* __restrict__ ni,
                            const float* __restrict__ w1s,
                            const float* __restrict__ w1v) {
    __shared__ float sWs[1024], sWv[1024];
    __shared__ float srow[8][128];
    int tid = threadIdx.x;
    {
        float4 z = make_float4(0.f, 0.f, 0.f, 0.f);
        size_t base = (size_t)blockIdx.x * 512;
        ((float4*)g_acc)[base + tid]       = z;
        ((float4*)g_acc)[base + 256 + tid] = z;
    }
    const float sc = 0.17677669529663687f;  // 1/sqrt(32)
    for (int i = tid; i < 1024; i += 256) { sWs[i] = w1s[i] * sc; sWv[i] = w1v[i] * sc; }
    __syncthreads();

    int warp = tid >> 5, lane = tid & 31;
    int node = blockIdx.x * 8 + warp;
    ((float4*)srow[warp])[lane] = ((const float4*)(ni + (size_t)node * 128))[lane];
    __syncwarp();

    float s = 0.f, v0 = 0.f, v1 = 0.f, v2 = 0.f;
#pragma unroll
    for (int u = 0; u < 32; u++) {
        float su = srow[warp][u];
        float a0 = srow[warp][32 + u * 3 + 0];
        float a1 = srow[warp][32 + u * 3 + 1];
        float a2 = srow[warp][32 + u * 3 + 2];
        float ws = sWs[u * 32 + lane];
        float wv = sWv[u * 32 + lane];
        s  = fmaf(su, ws, s);
        v0 = fmaf(a0, wv, v0);
        v1 = fmaf(a1, wv, v1);
        v2 = fmaf(a2, wv, v2);
    }
    ((float4*)(g_sv + (size_t)node * 128))[lane] = make_float4(s, v0, v1, v2);
}

// ---------------------------------------------------------------------------
// K2: edge kernel — R2 Phase A/B on SORTED contiguous edge arrays; Phase C
// register accumulation per dst-run, RED flush only on dst change.
// ---------------------------------------------------------------------------
#define EPW 8
__global__ void __launch_bounds__(128, 4)
edge_kernel(const float* __restrict__ fw1,
            const float* __restrict__ fw2) {
    __shared__ float sF1[512];
    __shared__ float sF2p[8192];
    __shared__ float h_sh[4][64 * EPW];
    int tid = threadIdx.x;
    for (int i = tid; i < 512; i += 128) sF1[i] = fw1[i] * 0.3535533905932738f;
    for (int i = tid; i < 8192; i += 128) {
        int j = i >> 7;
        int r = i & 127;
        int l = r >> 2, k = r & 3;
        sF2p[i] = fw2[j * 128 + k * 32 + l] * 0.125f;
    }
    __syncthreads();

    int lane = tid & 31, warp = tid >> 5;
    float* hs = h_sh[warp];
    int wg = blockIdx.x * 4 + warp;
    int nw = gridDim.x * 4;
    const int ngroups = N_EDGES / EPW;

    for (int g = wg; g < ngroups; g += nw) {
        int e0 = g * EPW;
        int src[EPW], dst[EPW];
        float es[EPW], evx[EPW], evy[EPW], evz[EPW];
        float h0[EPW], h1[EPW];

        // Phase A: SORTED contiguous edge loads + first MLP layer
#pragma unroll
        for (int e = 0; e < EPW; e++) {
            int ed = e0 + e;                 // sequential in sorted arrays
            int2 sd = g_ssd[ed];
            src[e] = sd.x;
            dst[e] = sd.y;
            float4 ea = g_sea[ed];
            es[e] = ea.x; evx[e] = ea.y; evy[e] = ea.z; evz[e] = ea.w;
            float4 sA = g_ses[ed * 2 + 0];
            float4 sB = g_ses[ed * 2 + 1];
            float sc8[8] = {sA.x, sA.y, sA.z, sA.w, sB.x, sB.y, sB.z, sB.w};
            float a0 = 0.f, a1 = 0.f;
#pragma unroll
            for (int i = 0; i < 8; i++) {
                a0 = fmaf(sc8[i], sF1[i * 64 + lane],      a0);
                a1 = fmaf(sc8[i], sF1[i * 64 + 32 + lane], a1);
            }
            h0[e] = silu_n(a0);
            h1[e] = silu_n(a1);
        }
        __syncwarp();
        ((float4*)hs)[lane * 2 + 0]      = make_float4(h0[0], h0[1], h0[2], h0[3]);
        ((float4*)hs)[lane * 2 + 1]      = make_float4(h0[4], h0[5], h0[6], h0[7]);
        ((float4*)hs)[64 + lane * 2 + 0] = make_float4(h1[0], h1[1], h1[2], h1[3]);
        ((float4*)hs)[64 + lane * 2 + 1] = make_float4(h1[4], h1[5], h1[6], h1[7]);
        __syncwarp();

        // Phase B: layer 2 with packed f32x2 FMA (R2-exact)
        unsigned long long w01[EPW], w23[EPW];
#pragma unroll
        for (int e = 0; e < EPW; e++) { w01[e] = 0ull; w23[e] = 0ull; }
#pragma unroll 8
        for (int j = 0; j < 64; j++) {
            float4 bw = ((const float4*)sF2p)[j * 32 + lane];
            unsigned long long b01 = pk(bw.x, bw.y);
            unsigned long long b23 = pk(bw.z, bw.w);
            float4 hA = ((const float4*)hs)[j * 2 + 0];
            float4 hB = ((const float4*)hs)[j * 2 + 1];
            float hv[EPW] = {hA.x, hA.y, hA.z, hA.w, hB.x, hB.y, hB.z, hB.w};
#pragma unroll
            for (int e = 0; e < EPW; e++) {
                unsigned long long hh = pk(hv[e], hv[e]);
                fma2(w01[e], hh, b01);
                fma2(w23[e], hh, b23);
            }
        }

        // Phase C: gather + tensor product; register accumulation per dst-run,
        // RED flush only when dst changes (edges are dst-sorted).
        int cur = dst[0];
        float A0 = 0.f, A1 = 0.f, A2 = 0.f, A3 = 0.f;
        float B0 = 0.f, B1 = 0.f, B2 = 0.f, B3 = 0.f;
#pragma unroll
        for (int e = 0; e < EPW; e++) {
            if (dst[e] != cur) {   // warp-uniform branch
                float* ar = g_acc + (size_t)cur * 256;
                red4(ar + lane * 4,       A0, A1, A2, A3);
                red4(ar + 128 + lane * 4, B0, B1, B2, B3);
                A0 = A1 = A2 = A3 = B0 = B1 = B2 = B3 = 0.f;
                cur = dst[e];
            }
            float4 q = ((const float4*)(g_sv + (size_t)src[e] * 128))[lane];
            float se = q.x, vx = q.y, vy = q.z, vz = q.w;
            float2 a01 = unpk(w01[e]);  // (w0, w1)
            float2 a23 = unpk(w23[e]);  // (w2, w3)
            float dotv = fmaf(vx, evx[e], fmaf(vy, evy[e], vz * evz[e]));
            float ms0 = a01.x * se * es[e];
            float ms1 = a23.y * dotv * 0.5773502691896258f;  // 1/sqrt(3)
            float aa  = a01.y * se;
            float bb  = a23.x * es[e];
            A0 += ms0;       A1 += aa * evx[e]; A2 += aa * evy[e]; A3 += aa * evz[e];
            B0 += ms1;       B1 += bb * vx;     B2 += bb * vy;     B3 += bb * vz;
        }
        {
            float* ar = g_acc + (size_t)cur * 256;
            red4(ar + lane * 4,       A0, A1, A2, A3);
            red4(ar + 128 + lane * 4, B0, B1, B2, B3);
        }
    }
}

// ---------------------------------------------------------------------------
// K3: lin2 — TRUE R2 version (measured 51us)
// ---------------------------------------------------------------------------
__global__ void lin2_kernel(const float* __restrict__ w2s,
                            const float* __restrict__ w2v,
                            float* __restrict__ out) {
    __shared__ float sW[4096];
    __shared__ float srow[8][256];
    int tid = threadIdx.x;
    const float sc = 0.03125f;
    for (int i = tid; i < 2048; i += 256) {
        sW[i * 2 + 0] = w2s[i] * sc;
        sW[i * 2 + 1] = w2v[i] * sc;
    }
    __syncthreads();

    int warp = tid >> 5, lane = tid & 31;
    int node = blockIdx.x * 8 + warp;

    const float4* ar = (const float4*)(g_acc + (size_t)node * 256);
    ((float4*)srow[warp])[lane]      = ar[lane];
    ((float4*)srow[warp])[lane + 32] = ar[lane + 32];
    __syncwarp();

    unsigned long long acc0 = 0ull, acc1 = 0ull;
#pragma unroll 8
    for (int u = 0; u < 64; u++) {
        float4 q = ((const float4*)srow[warp])[u];
        float2 wsv = ((const float2*)sW)[u * 32 + lane];
        fma2(acc0, pk(q.x, q.y), pk(wsv.x, wsv.y));
        fma2(acc1, pk(q.z, q.w), pk(wsv.y, wsv.y));
    }
    float2 r0 = unpk(acc0), r1 = unpk(acc1);
    float* o = out + (size_t)node * 128;
    o[lane] = r0.x;
    o[32 + lane * 3 + 0] = r0.y;
    o[32 + lane * 3 + 1] = r1.x;
    o[32 + lane * 3 + 2] = r1.y;
}

// ---------------------------------------------------------------------------
extern "C" void kernel_launch(void* const* d_in, const int* in_sizes, int n_in,
                              void* d_out, int out_size) {
    const float* node_input = (const float*)d_in[0];
    const int*   esrc  = (const int*)d_in[2];
    const int*   edst  = (const int*)d_in[3];
    const float* eattr = (const float*)d_in[4];
    const float* escal = (const float*)d_in[5];
    const float* w1s   = (const float*)d_in[6];
    const float* w1v   = (const float*)d_in[7];
    const float* fw1   = (const float*)d_in[8];
    const float* fw2   = (const float*)d_in[9];
    const float* w2s   = (const float*)d_in[10];
    const float* w2v   = (const float*)d_in[11];
    float* out = (float*)d_out;

    // binning pipeline: dst-sorted materialized edge arrays
    prep_zero_kernel<<<(NPAD + 255) / 256, 256>>>();
    hist_kernel<<<(N_EDGES + 255) / 256, 256>>>(edst);
    scan1_kernel<<<40, 1024>>>();
    scan2_kernel<<<1, 32>>>();
    scatter_kernel<<<(N_EDGES + 255) / 256, 256>>>(esrc, edst,
                                                   (const float4*)eattr,
                                                   (const float4*)escal);

    lin1_kernel<<<N_NODES / 8, 256>>>(node_input, w1s, w1v);
    edge_kernel<<<592, 128>>>(fw1, fw2);
    lin2_kernel<<<N_NODES / 8, 256>>>(w2s, w2v, out);
}

// round 12
// speedup vs baseline: 1.1875x; 1.1424x over previous
#include <cuda_runtime.h>
#include <cstdint>

#define N_NODES 40000
#define N_EDGES 640000
#define NPAD    40960

// Scratch (allocation-free rule: __device__ globals)
__device__ float g_sv[N_NODES * 128];    // lin1 out, quad: [node][lane]=(s,vx,vy,vz)
__device__ float g_acc[N_NODES * 256];   // aggregation, quad-interleaved
__device__ int   g_hist[NPAD];
__device__ int   g_start[NPAD];
__device__ int   g_cursor[NPAD];
__device__ int   g_bsum[40];
__device__ int   g_bscan[40];
// SORTED edge data (dst-ascending)
__device__ int2   g_ssd[N_EDGES];        // (src, dst)
__device__ float4 g_sea[N_EDGES];        // edge_attr
__device__ float4 g_ses[N_EDGES * 2];    // edge_scalars
// per-edge MLP output, packed: g_w[e*128 + lane*4 + c] = w_{c*32+lane}(e)
__device__ float  g_w[(size_t)N_EDGES * 128];

__device__ __forceinline__ float silu_n(float x) {
    return (x / (1.0f + __expf(-x))) * 1.6791767923989418f;
}
__device__ __forceinline__ unsigned long long pk(float a, float b) {
    unsigned long long r;
    asm("mov.b64 %0, {%1,%2};" : "=l"(r) : "f"(a), "f"(b));
    return r;
}
__device__ __forceinline__ void fma2(unsigned long long& d,
                                     unsigned long long a, unsigned long long b) {
    asm("fma.rn.f32x2 %0, %1, %2, %0;" : "+l"(d) : "l"(a), "l"(b));
}
__device__ __forceinline__ float2 unpk(unsigned long long v) {
    float2 r;
    asm("mov.b64 {%0,%1}, %2;" : "=f"(r.x), "=f"(r.y) : "l"(v));
    return r;
}
__device__ __forceinline__ void red4(float* p, float a, float b, float c, float d) {
    asm volatile("red.global.add.v4.f32 [%0], {%1,%2,%3,%4};"
                 :: "l"(p), "f"(a), "f"(b), "f"(c), "f"(d) : "memory");
}
__device__ __forceinline__ uint32_t tf32b(float x) {
    uint32_t r;
    asm("cvt.rna.tf32.f32 %0, %1;" : "=r"(r) : "f"(x));
    return r;
}
__device__ __forceinline__ void mma_tf32(float d[4], uint32_t a0, uint32_t a1,
                                         uint32_t a2, uint32_t a3,
                                         uint32_t b0, uint32_t b1) {
    asm volatile(
        "mma.sync.aligned.m16n8k8.row.col.f32.tf32.tf32.f32 "
        "{%0,%1,%2,%3}, {%4,%5,%6,%7}, {%8,%9}, {%0,%1,%2,%3};"
        : "+f"(d[0]), "+f"(d[1]), "+f"(d[2]), "+f"(d[3])
        : "r"(a0), "r"(a1), "r"(a2), "r"(a3), "r"(b0), "r"(b1));
}

// ---------------------------------------------------------------------------
// Binning pipeline (unchanged from R11, verified)
// ---------------------------------------------------------------------------
__global__ void prep_zero_kernel() {
    int i = blockIdx.x * blockDim.x + threadIdx.x;
    if (i < NPAD) { g_hist[i] = 0; g_cursor[i] = 0; }
}
__global__ void hist_kernel(const int* __restrict__ edst) {
    int e = blockIdx.x * blockDim.x + threadIdx.x;
    if (e < N_EDGES) atomicAdd(&g_hist[edst[e]], 1);
}
__global__ void scan1_kernel() {
    __shared__ int sh[1024];
    int tid = threadIdx.x;
    int i = blockIdx.x * 1024 + tid;
    int v = g_hist[i];
    sh[tid] = v;
    __syncthreads();
#pragma unroll
    for (int off = 1; off < 1024; off <<= 1) {
        int t = (tid >= off) ? sh[tid - off] : 0;
        __syncthreads();
        sh[tid] += t;
        __syncthreads();
    }
    g_start[i] = sh[tid] - v;
    if (tid == 1023) g_bsum[blockIdx.x] = sh[1023];
}
__global__ void scan2_kernel() {
    if (threadIdx.x == 0) {
        int s = 0;
#pragma unroll
        for (int b = 0; b < 40; b++) { g_bscan[b] = s; s += g_bsum[b]; }
    }
}
__global__ void scatter_kernel(const int*    __restrict__ esrc,
                               const int*    __restrict__ edst,
                               const float4* __restrict__ eattr,
                               const float4* __restrict__ escal) {
    int e = blockIdx.x * blockDim.x + threadIdx.x;
    if (e < N_EDGES) {
        int d = edst[e];
        int pos = g_start[d] + g_bscan[d >> 10] + atomicAdd(&g_cursor[d], 1);
        g_ssd[pos] = make_int2(esrc[e], d);
        g_sea[pos] = eattr[e];
        g_ses[pos * 2 + 0] = escal[e * 2 + 0];
        g_ses[pos * 2 + 1] = escal[e * 2 + 1];
    }
}

// ---------------------------------------------------------------------------
// w_gen: per-edge MLP on tensor cores.
// Per warp-tile: 16 edges. h = silu_n(escal @ fw1/sqrt8) computed scalar
// (lane = hidden), stored tf32 in smem; then m16n8k8 tf32 MMAs against a
// block-resident permuted fw2 fragment cache; W written packed to g_w.
// Dynamic smem (floats): Bfrag[8192] | hpad[4*1088] | sc[4*128] = 52224 B
// ---------------------------------------------------------------------------
#define WGEN_SMEM_FLOATS (8192 + 4 * 1088 + 4 * 128)
__global__ void __launch_bounds__(128)
wgen_kernel(const float* __restrict__ fw1, const float* __restrict__ fw2) {
    extern __shared__ float smem[];
    float* Bf   = smem;                 // [k][nt][lane][2] tf32 fragments
    float* hp   = smem + 8192;          // per-warp [16][68] tf32 h
    float* scb  = smem + 8192 + 4 * 1088;  // per-warp [16][8] escal
    int tid = threadIdx.x, lane = tid & 31, warp = tid >> 5;
    int gid = lane >> 2, qid = lane & 3;

    // build B fragment cache (once per block): b0/b1 for each (k,nt,lane)
    for (int idx = tid; idx < 8192; idx += 128) {
        int which = idx & 1;
        int lf    = (idx >> 1) & 31;
        int nt    = (idx >> 6) & 15;
        int k     = idx >> 10;
        int tf    = lf & 3, gf = lf >> 2;
        int j = k * 8 + tf + which * 4;      // K row
        int n = nt * 8 + gf;                 // packed output col
        int col = (n & 3) * 32 + (n >> 2);   // original fc_w2 col
        Bf[idx] = __uint_as_float(tf32b(fw2[j * 128 + col] * 0.125f));
    }
    // layer-1 weights in registers (lane = hidden)
    float wA[8], wB[8];
#pragma unroll
    for (int i = 0; i < 8; i++) {
        wA[i] = fw1[i * 64 + lane]      * 0.3535533905932738f;
        wB[i] = fw1[i * 64 + 32 + lane] * 0.3535533905932738f;
    }
    __syncthreads();

    float* hw  = hp  + warp * 1088;
    float* scw = scb + warp * 128;
    const int ntiles = N_EDGES / 16;

    for (int t = blockIdx.x * 4 + warp; t < ntiles; t += gridDim.x * 4) {
        int e0 = t * 16;
        // load 16 edges' scalars (32 float4 = 16 edges x 8)
        ((float4*)scw)[lane] = g_ses[(size_t)e0 * 2 + lane];
        __syncwarp();
        // layer 1: lane computes h[e][lane], h[e][lane+32]
#pragma unroll 4
        for (int e = 0; e < 16; e++) {
            const float* s8 = scw + e * 8;
            float a0 = 0.f, a1 = 0.f;
#pragma unroll
            for (int i = 0; i < 8; i++) {
                a0 = fmaf(s8[i], wA[i], a0);
                a1 = fmaf(s8[i], wB[i], a1);
            }
            hw[e * 68 + lane]      = __uint_as_float(tf32b(silu_n(a0)));
            hw[e * 68 + 32 + lane] = __uint_as_float(tf32b(silu_n(a1)));
        }
        __syncwarp();

        // MMA: D[16 edges x 128 packed outputs]
        float d[16][4];
#pragma unroll
        for (int nt = 0; nt < 16; nt++)
            d[nt][0] = d[nt][1] = d[nt][2] = d[nt][3] = 0.f;
#pragma unroll
        for (int k = 0; k < 8; k++) {
            uint32_t a0 = __float_as_uint(hw[gid * 68 + k * 8 + qid]);
            uint32_t a1 = __float_as_uint(hw[(gid + 8) * 68 + k * 8 + qid]);
            uint32_t a2 = __float_as_uint(hw[gid * 68 + k * 8 + qid + 4]);
            uint32_t a3 = __float_as_uint(hw[(gid + 8) * 68 + k * 8 + qid + 4]);
#pragma unroll
            for (int nt = 0; nt < 16; nt++) {
                float2 b = *(const float2*)(Bf + ((k * 16 + nt) * 32 + lane) * 2);
                mma_tf32(d[nt], a0, a1, a2, a3,
                         __float_as_uint(b.x), __float_as_uint(b.y));
            }
        }
        // store W packed: row=edge, col=packed output
#pragma unroll
        for (int nt = 0; nt < 16; nt++) {
            *(float2*)(g_w + (size_t)(e0 + gid) * 128 + nt * 8 + qid * 2)
                = make_float2(d[nt][0], d[nt][1]);
            *(float2*)(g_w + (size_t)(e0 + gid + 8) * 128 + nt * 8 + qid * 2)
                = make_float2(d[nt][2], d[nt][3]);
        }
        __syncwarp();
    }
}

// ---------------------------------------------------------------------------
// K1: lin1 (+ zero g_acc) — quad output layout
// ---------------------------------------------------------------------------
__global__ void lin1_kernel(const float* __restrict__ ni,
                            const float* __restrict__ w1s,
                            const float* __restrict__ w1v) {
    __shared__ float sWs[1024], sWv[1024];
    __shared__ float srow[8][128];
    int tid = threadIdx.x;
    {
        float4 z = make_float4(0.f, 0.f, 0.f, 0.f);
        size_t base = (size_t)blockIdx.x * 512;
        ((float4*)g_acc)[base + tid]       = z;
        ((float4*)g_acc)[base + 256 + tid] = z;
    }
    const float sc = 0.17677669529663687f;
    for (int i = tid; i < 1024; i += 256) { sWs[i] = w1s[i] * sc; sWv[i] = w1v[i] * sc; }
    __syncthreads();

    int warp = tid >> 5, lane = tid & 31;
    int node = blockIdx.x * 8 + warp;
    ((float4*)srow[warp])[lane] = ((const float4*)(ni + (size_t)node * 128))[lane];
    __syncwarp();

    float s = 0.f, v0 = 0.f, v1 = 0.f, v2 = 0.f;
#pragma unroll
    for (int u = 0; u < 32; u++) {
        float su = srow[warp][u];
        float a0 = srow[warp][32 + u * 3 + 0];
        float a1 = srow[warp][32 + u * 3 + 1];
        float a2 = srow[warp][32 + u * 3 + 2];
        float ws = sWs[u * 32 + lane];
        float wv = sWv[u * 32 + lane];
        s  = fmaf(su, ws, s);
        v0 = fmaf(a0, wv, v0);
        v1 = fmaf(a1, wv, v1);
        v2 = fmaf(a2, wv, v2);
    }
    ((float4*)(g_sv + (size_t)node * 128))[lane] = make_float4(s, v0, v1, v2);
}

// ---------------------------------------------------------------------------
// K2: edge kernel — NO MLP (w precomputed); sorted edges, dst-run RED flush.
// ---------------------------------------------------------------------------
#define EPW 8
__global__ void __launch_bounds__(128)
edge_kernel() {
    int tid = threadIdx.x, lane = tid & 31, warp = tid >> 5;
    int wg = blockIdx.x * 4 + warp;
    int nw = gridDim.x * 4;
    const int ngroups = N_EDGES / EPW;

    for (int g = wg; g < ngroups; g += nw) {
        int e0 = g * EPW;
        int src[EPW], dst[EPW];
        float4 eav[EPW], wv[EPW];
#pragma unroll
        for (int e = 0; e < EPW; e++) {
            int ed = e0 + e;
            int2 sd = g_ssd[ed];
            src[e] = sd.x;
            dst[e] = sd.y;
            eav[e] = g_sea[ed];
            wv[e]  = ((const float4*)g_w)[(size_t)ed * 32 + lane];
        }
        int cur = dst[0];
        float A0 = 0.f, A1 = 0.f, A2 = 0.f, A3 = 0.f;
        float B0 = 0.f, B1 = 0.f, B2 = 0.f, B3 = 0.f;
#pragma unroll
        for (int e = 0; e < EPW; e++) {
            if (dst[e] != cur) {   // warp-uniform
                float* ar = g_acc + (size_t)cur * 256;
                red4(ar + lane * 4,       A0, A1, A2, A3);
                red4(ar + 128 + lane * 4, B0, B1, B2, B3);
                A0 = A1 = A2 = A3 = B0 = B1 = B2 = B3 = 0.f;
                cur = dst[e];
            }
            float4 q = ((const float4*)(g_sv + (size_t)src[e] * 128))[lane];
            float se = q.x, vx = q.y, vy = q.z, vz = q.w;
            float4 ea = eav[e];
            float w0 = wv[e].x, w1 = wv[e].y, w2 = wv[e].z, w3 = wv[e].w;
            float dotv = fmaf(vx, ea.y, fmaf(vy, ea.z, vz * ea.w));
            float ms0 = w0 * se * ea.x;
            float ms1 = w3 * dotv * 0.5773502691896258f;
            float aa  = w1 * se;
            float bb  = w2 * ea.x;
            A0 += ms0; A1 += aa * ea.y; A2 += aa * ea.z; A3 += aa * ea.w;
            B0 += ms1; B1 += bb * vx;   B2 += bb * vy;   B3 += bb * vz;
        }
        {
            float* ar = g_acc + (size_t)cur * 256;
            red4(ar + lane * 4,       A0, A1, A2, A3);
            red4(ar + 128 + lane * 4, B0, B1, B2, B3);
        }
    }
}

// ---------------------------------------------------------------------------
// K3: lin2 — TRUE R2 version (measured 51us)
// ---------------------------------------------------------------------------
__global__ void lin2_kernel(const float* __restrict__ w2s,
                            const float* __restrict__ w2v,
                            float* __restrict__ out) {
    __shared__ float sW[4096];
    __shared__ float srow[8][256];
    int tid = threadIdx.x;
    const float sc = 0.03125f;
    for (int i = tid; i < 2048; i += 256) {
        sW[i * 2 + 0] = w2s[i] * sc;
        sW[i * 2 + 1] = w2v[i] * sc;
    }
    __syncthreads();

    int warp = tid >> 5, lane = tid & 31;
    int node = blockIdx.x * 8 + warp;

    const float4* ar = (const float4*)(g_acc + (size_t)node * 256);
    ((float4*)srow[warp])[lane]      = ar[lane];
    ((float4*)srow[warp])[lane + 32] = ar[lane + 32];
    __syncwarp();

    unsigned long long acc0 = 0ull, acc1 = 0ull;
#pragma unroll 8
    for (int u = 0; u < 64; u++) {
        float4 q = ((const float4*)srow[warp])[u];
        float2 wsv = ((const float2*)sW)[u * 32 + lane];
        fma2(acc0, pk(q.x, q.y), pk(wsv.x, wsv.y));
        fma2(acc1, pk(q.z, q.w), pk(wsv.y, wsv.y));
    }
    float2 r0 = unpk(acc0), r1 = unpk(acc1);
    float* o = out + (size_t)node * 128;
    o[lane] = r0.x;
    o[32 + lane * 3 + 0] = r0.y;
    o[32 + lane * 3 + 1] = r1.x;
    o[32 + lane * 3 + 2] = r1.y;
}

// ---------------------------------------------------------------------------
extern "C" void kernel_launch(void* const* d_in, const int* in_sizes, int n_in,
                              void* d_out, int out_size) {
    const float* node_input = (const float*)d_in[0];
    const int*   esrc  = (const int*)d_in[2];
    const int*   edst  = (const int*)d_in[3];
    const float* eattr = (const float*)d_in[4];
    const float* escal = (const float*)d_in[5];
    const float* w1s   = (const float*)d_in[6];
    const float* w1v   = (const float*)d_in[7];
    const float* fw1   = (const float*)d_in[8];
    const float* fw2   = (const float*)d_in[9];
    const float* w2s   = (const float*)d_in[10];
    const float* w2v   = (const float*)d_in[11];
    float* out = (float*)d_out;

    static bool attr_set = false;
    if (!attr_set) {
        cudaFuncSetAttribute(wgen_kernel,
                             cudaFuncAttributeMaxDynamicSharedMemorySize,
                             WGEN_SMEM_FLOATS * 4);
        attr_set = true;
    }

    prep_zero_kernel<<<(NPAD + 255) / 256, 256>>>();
    hist_kernel<<<(N_EDGES + 255) / 256, 256>>>(edst);
    scan1_kernel<<<40, 1024>>>();
    scan2_kernel<<<1, 32>>>();
    scatter_kernel<<<(N_EDGES + 255) / 256, 256>>>(esrc, edst,
                                                   (const float4*)eattr,
                                                   (const float4*)escal);
    wgen_kernel<<<592, 128, WGEN_SMEM_FLOATS * 4>>>(fw1, fw2);
    lin1_kernel<<<N_NODES / 8, 256>>>(node_input, w1s, w1v);
    edge_kernel<<<592, 128>>>();
    lin2_kernel<<<N_NODES / 8, 256>>>(w2s, w2v, out);
}

// round 13
// speedup vs baseline: 1.3358x; 1.1249x over previous
#include <cuda_runtime.h>
#include <cstdint>

#define N_NODES 40000
#define N_EDGES 640000
#define NPAD    40960

// Scratch (allocation-free rule: __device__ globals)
__device__ float g_sv[N_NODES * 128];    // lin1 out, quad: [node][lane]=(s,vx,vy,vz)
__device__ float g_acc[N_NODES * 256];   // aggregation, quad-interleaved
__device__ int   g_hist[NPAD];
__device__ int   g_start[NPAD];
__device__ int   g_cursor[NPAD];
__device__ int   g_bsum[40];
__device__ int   g_bscan[40];
// SORTED edge data (dst-ascending)
__device__ int2   g_ssd[N_EDGES];        // (src, dst)
__device__ float4 g_sea[N_EDGES];        // edge_attr
__device__ float4 g_ses[N_EDGES * 2];    // edge_scalars

__device__ __forceinline__ float silu_n(float x) {
    return (x / (1.0f + __expf(-x))) * 1.6791767923989418f;
}
__device__ __forceinline__ unsigned long long pk(float a, float b) {
    unsigned long long r;
    asm("mov.b64 %0, {%1,%2};" : "=l"(r) : "f"(a), "f"(b));
    return r;
}
__device__ __forceinline__ void fma2(unsigned long long& d,
                                     unsigned long long a, unsigned long long b) {
    asm("fma.rn.f32x2 %0, %1, %2, %0;" : "+l"(d) : "l"(a), "l"(b));
}
__device__ __forceinline__ float2 unpk(unsigned long long v) {
    float2 r;
    asm("mov.b64 {%0,%1}, %2;" : "=f"(r.x), "=f"(r.y) : "l"(v));
    return r;
}
__device__ __forceinline__ void red4(float* p, float a, float b, float c, float d) {
    asm volatile("red.global.add.v4.f32 [%0], {%1,%2,%3,%4};"
                 :: "l"(p), "f"(a), "f"(b), "f"(c), "f"(d) : "memory");
}
__device__ __forceinline__ uint32_t tf32b(float x) {
    uint32_t r;
    asm("cvt.rna.tf32.f32 %0, %1;" : "=r"(r) : "f"(x));
    return r;
}
__device__ __forceinline__ void mma_tf32(float d[4], uint32_t a0, uint32_t a1,
                                         uint32_t a2, uint32_t a3,
                                         uint32_t b0, uint32_t b1) {
    asm volatile(
        "mma.sync.aligned.m16n8k8.row.col.f32.tf32.tf32.f32 "
        "{%0,%1,%2,%3}, {%4,%5,%6,%7}, {%8,%9}, {%0,%1,%2,%3};"
        : "+f"(d[0]), "+f"(d[1]), "+f"(d[2]), "+f"(d[3])
        : "r"(a0), "r"(a1), "r"(a2), "r"(a3), "r"(b0), "r"(b1));
}

// ---------------------------------------------------------------------------
// Binning pipeline (verified in R11/R12)
// ---------------------------------------------------------------------------
__global__ void prep_zero_kernel() {
    int i = blockIdx.x * blockDim.x + threadIdx.x;
    if (i < NPAD) { g_hist[i] = 0; g_cursor[i] = 0; }
}
__global__ void hist_kernel(const int* __restrict__ edst) {
    int e = blockIdx.x * blockDim.x + threadIdx.x;
    if (e < N_EDGES) atomicAdd(&g_hist[edst[e]], 1);
}
__global__ void scan1_kernel() {
    __shared__ int sh[1024];
    int tid = threadIdx.x;
    int i = blockIdx.x * 1024 + tid;
    int v = g_hist[i];
    sh[tid] = v;
    __syncthreads();
#pragma unroll
    for (int off = 1; off < 1024; off <<= 1) {
        int t = (tid >= off) ? sh[tid - off] : 0;
        __syncthreads();
        sh[tid] += t;
        __syncthreads();
    }
    g_start[i] = sh[tid] - v;
    if (tid == 1023) g_bsum[blockIdx.x] = sh[1023];
}
__global__ void scan2_kernel() {
    if (threadIdx.x == 0) {
        int s = 0;
#pragma unroll
        for (int b = 0; b < 40; b++) { g_bscan[b] = s; s += g_bsum[b]; }
    }
}
__global__ void scatter_kernel(const int*    __restrict__ esrc,
                               const int*    __restrict__ edst,
                               const float4* __restrict__ eattr,
                               const float4* __restrict__ escal) {
    int e = blockIdx.x * blockDim.x + threadIdx.x;
    if (e < N_EDGES) {
        int d = edst[e];
        int pos = g_start[d] + g_bscan[d >> 10] + atomicAdd(&g_cursor[d], 1);
        g_ssd[pos] = make_int2(esrc[e], d);
        g_sea[pos] = eattr[e];
        g_ses[pos * 2 + 0] = escal[e * 2 + 0];
        g_ses[pos * 2 + 1] = escal[e * 2 + 1];
    }
}

// ---------------------------------------------------------------------------
// K1: lin1 (+ zero g_acc) — quad output layout
// ---------------------------------------------------------------------------
__global__ void lin1_kernel(const float* __restrict__ ni,
                            const float* __restrict__ w1s,
                            const float* __restrict__ w1v) {
    __shared__ float sWs[1024], sWv[1024];
    __shared__ float srow[8][128];
    int tid = threadIdx.x;
    {
        float4 z = make_float4(0.f, 0.f, 0.f, 0.f);
        size_t base = (size_t)blockIdx.x * 512;
        ((float4*)g_acc)[base + tid]       = z;
        ((float4*)g_acc)[base + 256 + tid] = z;
    }
    const float sc = 0.17677669529663687f;
    for (int i = tid; i < 1024; i += 256) { sWs[i] = w1s[i] * sc; sWv[i] = w1v[i] * sc; }
    __syncthreads();

    int warp = tid >> 5, lane = tid & 31;
    int node = blockIdx.x * 8 + warp;
    ((float4*)srow[warp])[lane] = ((const float4*)(ni + (size_t)node * 128))[lane];
    __syncwarp();

    float s = 0.f, v0 = 0.f, v1 = 0.f, v2 = 0.f;
#pragma unroll
    for (int u = 0; u < 32; u++) {
        float su = srow[warp][u];
        float a0 = srow[warp][32 + u * 3 + 0];
        float a1 = srow[warp][32 + u * 3 + 1];
        float a2 = srow[warp][32 + u * 3 + 2];
        float ws = sWs[u * 32 + lane];
        float wv = sWv[u * 32 + lane];
        s  = fmaf(su, ws, s);
        v0 = fmaf(a0, wv, v0);
        v1 = fmaf(a1, wv, v1);
        v2 = fmaf(a2, wv, v2);
    }
    ((float4*)(g_sv + (size_t)node * 128))[lane] = make_float4(s, v0, v1, v2);
}

// ---------------------------------------------------------------------------
// K2 (FUSED): per warp-tile of 16 sorted edges:
//   layer-1 scalar -> tf32 h in smem -> m16n8k8 tf32 MMAs (R12-verified)
//   -> w staged to smem (rows padded to 136 floats; conflict-free)
//   -> Phase C gather + tensor product + dst-run RED flush.
// Per-warp scratch (2176 floats) unions {escal(128)+h(1088)} with w-stage.
// Smem: Bf(8192) + 4*2176 = 16896 floats = 66 KB -> 3 blocks/SM.
// ---------------------------------------------------------------------------
#define WST 136  // padded row stride for w stage
#define EDGE_SMEM_FLOATS (8192 + 4 * (16 * WST))

__global__ void __launch_bounds__(128)
edge_kernel(const float* __restrict__ fw1, const float* __restrict__ fw2) {
    extern __shared__ float smem[];
    float* Bf  = smem;                          // [k][nt][lane][2] tf32 B fragments
    int tid = threadIdx.x, lane = tid & 31, warp = tid >> 5;
    int gid = lane >> 2, qid = lane & 3;
    float* wsc = smem + 8192 + warp * (16 * WST);  // per-warp scratch

    // build B fragment cache (once per block) — identical to R12 wgen
    for (int idx = tid; idx < 8192; idx += 128) {
        int which = idx & 1;
        int lf    = (idx >> 1) & 31;
        int nt    = (idx >> 6) & 15;
        int k     = idx >> 10;
        int tf    = lf & 3, gf = lf >> 2;
        int j = k * 8 + tf + which * 4;
        int n = nt * 8 + gf;
        int col = (n & 3) * 32 + (n >> 2);
        Bf[idx] = __uint_as_float(tf32b(fw2[j * 128 + col] * 0.125f));
    }
    // layer-1 weights in registers (lane = hidden unit)
    float wA[8], wB[8];
#pragma unroll
    for (int i = 0; i < 8; i++) {
        wA[i] = fw1[i * 64 + lane]      * 0.3535533905932738f;
        wB[i] = fw1[i * 64 + 32 + lane] * 0.3535533905932738f;
    }
    __syncthreads();

    const int ntiles = N_EDGES / 16;
    for (int t = blockIdx.x * 4 + warp; t < ntiles; t += gridDim.x * 4) {
        int e0 = t * 16;
        float* scw = wsc;          // escal stage [16][8]
        float* hw  = wsc + 128;    // tf32 h [16][68]

        // prefetch src/dst early (independent of MLP)
        int2 sd[16];
#pragma unroll
        for (int e = 0; e < 16; e++) sd[e] = g_ssd[e0 + e];

        // stage escal, layer 1
        ((float4*)scw)[lane] = g_ses[(size_t)e0 * 2 + lane];
        __syncwarp();
#pragma unroll 4
        for (int e = 0; e < 16; e++) {
            const float* s8 = scw + e * 8;
            float a0 = 0.f, a1 = 0.f;
#pragma unroll
            for (int i = 0; i < 8; i++) {
                a0 = fmaf(s8[i], wA[i], a0);
                a1 = fmaf(s8[i], wB[i], a1);
            }
            hw[e * 68 + lane]      = __uint_as_float(tf32b(silu_n(a0)));
            hw[e * 68 + 32 + lane] = __uint_as_float(tf32b(silu_n(a1)));
        }
        __syncwarp();

        // MMA: D[16 edges x 128 packed outputs] — identical to R12 wgen
        float d[16][4];
#pragma unroll
        for (int nt = 0; nt < 16; nt++)
            d[nt][0] = d[nt][1] = d[nt][2] = d[nt][3] = 0.f;
#pragma unroll
        for (int k = 0; k < 8; k++) {
            uint32_t a0 = __float_as_uint(hw[gid * 68 + k * 8 + qid]);
            uint32_t a1 = __float_as_uint(hw[(gid + 8) * 68 + k * 8 + qid]);
            uint32_t a2 = __float_as_uint(hw[gid * 68 + k * 8 + qid + 4]);
            uint32_t a3 = __float_as_uint(hw[(gid + 8) * 68 + k * 8 + qid + 4]);
#pragma unroll
            for (int nt = 0; nt < 16; nt++) {
                float2 b = *(const float2*)(Bf + ((k * 16 + nt) * 32 + lane) * 2);
                mma_tf32(d[nt], a0, a1, a2, a3,
                         __float_as_uint(b.x), __float_as_uint(b.y));
            }
        }
        __syncwarp();   // hw dead; reuse scratch as w stage

        // stage w to smem: row e (stride WST), packed col layout as R12
        float* wst = wsc;
#pragma unroll
        for (int nt = 0; nt < 16; nt++) {
            *(float2*)(wst + (size_t)gid * WST + nt * 8 + qid * 2)
                = make_float2(d[nt][0], d[nt][1]);
            *(float2*)(wst + (size_t)(gid + 8) * WST + nt * 8 + qid * 2)
                = make_float2(d[nt][2], d[nt][3]);
        }
        __syncwarp();

        // Phase C: gather + tensor product; dst-run register accumulation
        int cur = sd[0].y;
        float A0 = 0.f, A1 = 0.f, A2 = 0.f, A3 = 0.f;
        float B0 = 0.f, B1 = 0.f, B2 = 0.f, B3 = 0.f;
#pragma unroll
        for (int e = 0; e < 16; e++) {
            if (sd[e].y != cur) {   // warp-uniform
                float* ar = g_acc + (size_t)cur * 256;
                red4(ar + lane * 4,       A0, A1, A2, A3);
                red4(ar + 128 + lane * 4, B0, B1, B2, B3);
                A0 = A1 = A2 = A3 = B0 = B1 = B2 = B3 = 0.f;
                cur = sd[e].y;
            }
            float4 ea = g_sea[e0 + e];
            float4 q  = ((const float4*)(g_sv + (size_t)sd[e].x * 128))[lane];
            float4 wq = *(const float4*)(wst + e * WST + lane * 4);
            float se = q.x, vx = q.y, vy = q.z, vz = q.w;
            float dotv = fmaf(vx, ea.y, fmaf(vy, ea.z, vz * ea.w));
            float ms0 = wq.x * se * ea.x;
            float ms1 = wq.w * dotv * 0.5773502691896258f;
            float aa  = wq.y * se;
            float bb  = wq.z * ea.x;
            A0 += ms0; A1 += aa * ea.y; A2 += aa * ea.z; A3 += aa * ea.w;
            B0 += ms1; B1 += bb * vx;   B2 += bb * vy;   B3 += bb * vz;
        }
        {
            float* ar = g_acc + (size_t)cur * 256;
            red4(ar + lane * 4,       A0, A1, A2, A3);
            red4(ar + 128 + lane * 4, B0, B1, B2, B3);
        }
        __syncwarp();   // wst reads done before next tile overwrites scratch
    }
}

// ---------------------------------------------------------------------------
// K3: lin2 — TRUE R2 version (measured 51us)
// ---------------------------------------------------------------------------
__global__ void lin2_kernel(const float* __restrict__ w2s,
                            const float* __restrict__ w2v,
                            float* __restrict__ out) {
    __shared__ float sW[4096];
    __shared__ float srow[8][256];
    int tid = threadIdx.x;
    const float sc = 0.03125f;
    for (int i = tid; i < 2048; i += 256) {
        sW[i * 2 + 0] = w2s[i] * sc;
        sW[i * 2 + 1] = w2v[i] * sc;
    }
    __syncthreads();

    int warp = tid >> 5, lane = tid & 31;
    int node = blockIdx.x * 8 + warp;

    const float4* ar = (const float4*)(g_acc + (size_t)node * 256);
    ((float4*)srow[warp])[lane]      = ar[lane];
    ((float4*)srow[warp])[lane + 32] = ar[lane + 32];
    __syncwarp();

    unsigned long long acc0 = 0ull, acc1 = 0ull;
#pragma unroll 8
    for (int u = 0; u < 64; u++) {
        float4 q = ((const float4*)srow[warp])[u];
        float2 wsv = ((const float2*)sW)[u * 32 + lane];
        fma2(acc0, pk(q.x, q.y), pk(wsv.x, wsv.y));
        fma2(acc1, pk(q.z, q.w), pk(wsv.y, wsv.y));
    }
    float2 r0 = unpk(acc0), r1 = unpk(acc1);
    float* o = out + (size_t)node * 128;
    o[lane] = r0.x;
    o[32 + lane * 3 + 0] = r0.y;
    o[32 + lane * 3 + 1] = r1.x;
    o[32 + lane * 3 + 2] = r1.y;
}

// ---------------------------------------------------------------------------
extern "C" void kernel_launch(void* const* d_in, const int* in_sizes, int n_in,
                              void* d_out, int out_size) {
    const float* node_input = (const float*)d_in[0];
    const int*   esrc  = (const int*)d_in[2];
    const int*   edst  = (const int*)d_in[3];
    const float* eattr = (const float*)d_in[4];
    const float* escal = (const float*)d_in[5];
    const float* w1s   = (const float*)d_in[6];
    const float* w1v   = (const float*)d_in[7];
    const float* fw1   = (const float*)d_in[8];
    const float* fw2   = (const float*)d_in[9];
    const float* w2s   = (const float*)d_in[10];
    const float* w2v   = (const float*)d_in[11];
    float* out = (float*)d_out;

    static bool attr_set = false;
    if (!attr_set) {
        cudaFuncSetAttribute(edge_kernel,
                             cudaFuncAttributeMaxDynamicSharedMemorySize,
                             EDGE_SMEM_FLOATS * 4);
        attr_set = true;
    }

    prep_zero_kernel<<<(NPAD + 255) / 256, 256>>>();
    hist_kernel<<<(N_EDGES + 255) / 256, 256>>>(edst);
    scan1_kernel<<<40, 1024>>>();
    scan2_kernel<<<1, 32>>>();
    scatter_kernel<<<(N_EDGES + 255) / 256, 256>>>(esrc, edst,
                                                   (const float4*)eattr,
                                                   (const float4*)escal);
    lin1_kernel<<<N_NODES / 8, 256>>>(node_input, w1s, w1v);
    edge_kernel<<<444, 128, EDGE_SMEM_FLOATS * 4>>>(fw1, fw2);
    lin2_kernel<<<N_NODES / 8, 256>>>(w2s, w2v, out);
}

// round 14
// speedup vs baseline: 1.4396x; 1.0777x over previous
#include <cuda_runtime.h>
#include <cstdint>

#define N_NODES 40000
#define N_EDGES 640000
#define NPAD    40960

// Scratch (allocation-free rule: __device__ globals)
__device__ float g_sv[N_NODES * 128];    // lin1 out, quad: [node][lane]=(s,vx,vy,vz)
__device__ float g_acc[N_NODES * 256];   // aggregation, quad-interleaved
__device__ int   g_hist[NPAD];
__device__ int   g_start[NPAD];
__device__ int   g_cursor[NPAD];
__device__ int   g_bsum[40];
// SORTED edge data (dst-ascending)
__device__ int2   g_ssd[N_EDGES];        // (src, dst)
__device__ float4 g_sea[N_EDGES];        // edge_attr
__device__ float4 g_ses[N_EDGES * 2];    // edge_scalars

__device__ __forceinline__ float silu_n(float x) {
    return (x / (1.0f + __expf(-x))) * 1.6791767923989418f;
}
__device__ __forceinline__ unsigned long long pk(float a, float b) {
    unsigned long long r;
    asm("mov.b64 %0, {%1,%2};" : "=l"(r) : "f"(a), "f"(b));
    return r;
}
__device__ __forceinline__ void fma2(unsigned long long& d,
                                     unsigned long long a, unsigned long long b) {
    asm("fma.rn.f32x2 %0, %1, %2, %0;" : "+l"(d) : "l"(a), "l"(b));
}
__device__ __forceinline__ float2 unpk(unsigned long long v) {
    float2 r;
    asm("mov.b64 {%0,%1}, %2;" : "=f"(r.x), "=f"(r.y) : "l"(v));
    return r;
}
__device__ __forceinline__ void red4(float* p, float a, float b, float c, float d) {
    asm volatile("red.global.add.v4.f32 [%0], {%1,%2,%3,%4};"
                 :: "l"(p), "f"(a), "f"(b), "f"(c), "f"(d) : "memory");
}
__device__ __forceinline__ uint32_t tf32b(float x) {
    uint32_t r;
    asm("cvt.rna.tf32.f32 %0, %1;" : "=r"(r) : "f"(x));
    return r;
}
__device__ __forceinline__ void mma_tf32(float d[4], uint32_t a0, uint32_t a1,
                                         uint32_t a2, uint32_t a3,
                                         uint32_t b0, uint32_t b1) {
    asm volatile(
        "mma.sync.aligned.m16n8k8.row.col.f32.tf32.tf32.f32 "
        "{%0,%1,%2,%3}, {%4,%5,%6,%7}, {%8,%9}, {%0,%1,%2,%3};"
        : "+f"(d[0]), "+f"(d[1]), "+f"(d[2]), "+f"(d[3])
        : "r"(a0), "r"(a1), "r"(a2), "r"(a3), "r"(b0), "r"(b1));
}

// ---------------------------------------------------------------------------
// Binning pipeline (scan2 folded into scatter)
// ---------------------------------------------------------------------------
__global__ void prep_zero_kernel() {
    int i = blockIdx.x * blockDim.x + threadIdx.x;
    if (i < NPAD) { g_hist[i] = 0; g_cursor[i] = 0; }
}
__global__ void hist_kernel(const int* __restrict__ edst) {
    int e = blockIdx.x * blockDim.x + threadIdx.x;
    if (e < N_EDGES) atomicAdd(&g_hist[edst[e]], 1);
}
__global__ void scan1_kernel() {
    __shared__ int sh[1024];
    int tid = threadIdx.x;
    int i = blockIdx.x * 1024 + tid;
    int v = g_hist[i];
    sh[tid] = v;
    __syncthreads();
#pragma unroll
    for (int off = 1; off < 1024; off <<= 1) {
        int t = (tid >= off) ? sh[tid - off] : 0;
        __syncthreads();
        sh[tid] += t;
        __syncthreads();
    }
    g_start[i] = sh[tid] - v;
    if (tid == 1023) g_bsum[blockIdx.x] = sh[1023];
}
// scatter: per-block prefix of the 40 block sums + sorted copies of edge data
__global__ void scatter_kernel(const int*    __restrict__ esrc,
                               const int*    __restrict__ edst,
                               const float4* __restrict__ eattr,
                               const float4* __restrict__ escal) {
    __shared__ int sb[40];
    int tid = threadIdx.x;
    if (tid < 40) sb[tid] = g_bsum[tid];
    __syncthreads();
    if (tid == 0) {
        int s = 0;
#pragma unroll
        for (int b = 0; b < 40; b++) { int v = sb[b]; sb[b] = s; s += v; }
    }
    __syncthreads();
    int e = blockIdx.x * blockDim.x + tid;
    if (e < N_EDGES) {
        int d = edst[e];
        int pos = g_start[d] + sb[d >> 10] + atomicAdd(&g_cursor[d], 1);
        g_ssd[pos] = make_int2(esrc[e], d);
        g_sea[pos] = eattr[e];
        g_ses[pos * 2 + 0] = escal[e * 2 + 0];
        g_ses[pos * 2 + 1] = escal[e * 2 + 1];
    }
}

// ---------------------------------------------------------------------------
// K1: lin1 (+ zero g_acc) — quad output layout
// ---------------------------------------------------------------------------
__global__ void lin1_kernel(const float* __restrict__ ni,
                            const float* __restrict__ w1s,
                            const float* __restrict__ w1v) {
    __shared__ float sWs[1024], sWv[1024];
    __shared__ float srow[8][128];
    int tid = threadIdx.x;
    {
        float4 z = make_float4(0.f, 0.f, 0.f, 0.f);
        size_t base = (size_t)blockIdx.x * 512;
        ((float4*)g_acc)[base + tid]       = z;
        ((float4*)g_acc)[base + 256 + tid] = z;
    }
    const float sc = 0.17677669529663687f;
    for (int i = tid; i < 1024; i += 256) { sWs[i] = w1s[i] * sc; sWv[i] = w1v[i] * sc; }
    __syncthreads();

    int warp = tid >> 5, lane = tid & 31;
    int node = blockIdx.x * 8 + warp;
    ((float4*)srow[warp])[lane] = ((const float4*)(ni + (size_t)node * 128))[lane];
    __syncwarp();

    float s = 0.f, v0 = 0.f, v1 = 0.f, v2 = 0.f;
#pragma unroll
    for (int u = 0; u < 32; u++) {
        float su = srow[warp][u];
        float a0 = srow[warp][32 + u * 3 + 0];
        float a1 = srow[warp][32 + u * 3 + 1];
        float a2 = srow[warp][32 + u * 3 + 2];
        float ws = sWs[u * 32 + lane];
        float wv = sWv[u * 32 + lane];
        s  = fmaf(su, ws, s);
        v0 = fmaf(a0, wv, v0);
        v1 = fmaf(a1, wv, v1);
        v2 = fmaf(a2, wv, v2);
    }
    ((float4*)(g_sv + (size_t)node * 128))[lane] = make_float4(s, v0, v1, v2);
}

// ---------------------------------------------------------------------------
// K2 (FUSED): per warp-tile of 16 sorted edges. Same as R13, ONE change:
// the g_sv gathers are PREFETCHED (8 before the MLP/MMA, 8 right after the
// MMA) so their ~600-cycle latency hides behind the math.
// ---------------------------------------------------------------------------
#define WST 136
#define EDGE_SMEM_FLOATS (8192 + 4 * (16 * WST))

__global__ void __launch_bounds__(128, 3)
edge_kernel(const float* __restrict__ fw1, const float* __restrict__ fw2) {
    extern __shared__ float smem[];
    float* Bf  = smem;                          // [k][nt][lane][2] tf32 B fragments
    int tid = threadIdx.x, lane = tid & 31, warp = tid >> 5;
    int gid = lane >> 2, qid = lane & 3;
    float* wsc = smem + 8192 + warp * (16 * WST);

    for (int idx = tid; idx < 8192; idx += 128) {
        int which = idx & 1;
        int lf    = (idx >> 1) & 31;
        int nt    = (idx >> 6) & 15;
        int k     = idx >> 10;
        int tf    = lf & 3, gf = lf >> 2;
        int j = k * 8 + tf + which * 4;
        int n = nt * 8 + gf;
        int col = (n & 3) * 32 + (n >> 2);
        Bf[idx] = __uint_as_float(tf32b(fw2[j * 128 + col] * 0.125f));
    }
    float wA[8], wB[8];
#pragma unroll
    for (int i = 0; i < 8; i++) {
        wA[i] = fw1[i * 64 + lane]      * 0.3535533905932738f;
        wB[i] = fw1[i * 64 + 32 + lane] * 0.3535533905932738f;
    }
    __syncthreads();

    const int ntiles = N_EDGES / 16;
    for (int t = blockIdx.x * 4 + warp; t < ntiles; t += gridDim.x * 4) {
        int e0 = t * 16;
        float* scw = wsc;          // escal stage [16][8]
        float* hw  = wsc + 128;    // tf32 h [16][68]

        // prefetch src/dst and FIRST 8 gathers (independent of MLP)
        int2 sd[16];
#pragma unroll
        for (int e = 0; e < 16; e++) sd[e] = g_ssd[e0 + e];
        float4 qv[8];
#pragma unroll
        for (int e = 0; e < 8; e++)
            qv[e] = ((const float4*)(g_sv + (size_t)sd[e].x * 128))[lane];

        // stage escal, layer 1
        ((float4*)scw)[lane] = g_ses[(size_t)e0 * 2 + lane];
        __syncwarp();
#pragma unroll 4
        for (int e = 0; e < 16; e++) {
            const float* s8 = scw + e * 8;
            float a0 = 0.f, a1 = 0.f;
#pragma unroll
            for (int i = 0; i < 8; i++) {
                a0 = fmaf(s8[i], wA[i], a0);
                a1 = fmaf(s8[i], wB[i], a1);
            }
            hw[e * 68 + lane]      = __uint_as_float(tf32b(silu_n(a0)));
            hw[e * 68 + 32 + lane] = __uint_as_float(tf32b(silu_n(a1)));
        }
        __syncwarp();

        // MMA: D[16 edges x 128 packed outputs]
        float d[16][4];
#pragma unroll
        for (int nt = 0; nt < 16; nt++)
            d[nt][0] = d[nt][1] = d[nt][2] = d[nt][3] = 0.f;
#pragma unroll
        for (int k = 0; k < 8; k++) {
            uint32_t a0 = __float_as_uint(hw[gid * 68 + k * 8 + qid]);
            uint32_t a1 = __float_as_uint(hw[(gid + 8) * 68 + k * 8 + qid]);
            uint32_t a2 = __float_as_uint(hw[gid * 68 + k * 8 + qid + 4]);
            uint32_t a3 = __float_as_uint(hw[(gid + 8) * 68 + k * 8 + qid + 4]);
#pragma unroll
            for (int nt = 0; nt < 16; nt++) {
                float2 b = *(const float2*)(Bf + ((k * 16 + nt) * 32 + lane) * 2);
                mma_tf32(d[nt], a0, a1, a2, a3,
                         __float_as_uint(b.x), __float_as_uint(b.y));
            }
        }
        __syncwarp();   // hw dead; reuse scratch as w stage

        // prefetch SECOND 8 gathers (latency hidden by staging + chunk A)
        float4 qv2[8];
#pragma unroll
        for (int e = 0; e < 8; e++)
            qv2[e] = ((const float4*)(g_sv + (size_t)sd[8 + e].x * 128))[lane];

        // stage w to smem
        float* wst = wsc;
#pragma unroll
        for (int nt = 0; nt < 16; nt++) {
            *(float2*)(wst + (size_t)gid * WST + nt * 8 + qid * 2)
                = make_float2(d[nt][0], d[nt][1]);
            *(float2*)(wst + (size_t)(gid + 8) * WST + nt * 8 + qid * 2)
                = make_float2(d[nt][2], d[nt][3]);
        }
        __syncwarp();

        // Phase C: tensor product + dst-run register accumulation
        int cur = sd[0].y;
        float A0 = 0.f, A1 = 0.f, A2 = 0.f, A3 = 0.f;
        float B0 = 0.f, B1 = 0.f, B2 = 0.f, B3 = 0.f;
#pragma unroll
        for (int e = 0; e < 16; e++) {
            if (sd[e].y != cur) {   // warp-uniform
                float* ar = g_acc + (size_t)cur * 256;
                red4(ar + lane * 4,       A0, A1, A2, A3);
                red4(ar + 128 + lane * 4, B0, B1, B2, B3);
                A0 = A1 = A2 = A3 = B0 = B1 = B2 = B3 = 0.f;
                cur = sd[e].y;
            }
            float4 ea = g_sea[e0 + e];
            float4 q  = (e < 8) ? qv[e & 7] : qv2[e & 7];
            float4 wq = *(const float4*)(wst + e * WST + lane * 4);
            float se = q.x, vx = q.y, vy = q.z, vz = q.w;
            float dotv = fmaf(vx, ea.y, fmaf(vy, ea.z, vz * ea.w));
            float ms0 = wq.x * se * ea.x;
            float ms1 = wq.w * dotv * 0.5773502691896258f;
            float aa  = wq.y * se;
            float bb  = wq.z * ea.x;
            A0 += ms0; A1 += aa * ea.y; A2 += aa * ea.z; A3 += aa * ea.w;
            B0 += ms1; B1 += bb * vx;   B2 += bb * vy;   B3 += bb * vz;
        }
        {
            float* ar = g_acc + (size_t)cur * 256;
            red4(ar + lane * 4,       A0, A1, A2, A3);
            red4(ar + 128 + lane * 4, B0, B1, B2, B3);
        }
        __syncwarp();
    }
}

// ---------------------------------------------------------------------------
// K3: lin2 — TRUE R2 version (measured 51us)
// ---------------------------------------------------------------------------
__global__ void lin2_kernel(const float* __restrict__ w2s,
                            const float* __restrict__ w2v,
                            float* __restrict__ out) {
    __shared__ float sW[4096];
    __shared__ float srow[8][256];
    int tid = threadIdx.x;
    const float sc = 0.03125f;
    for (int i = tid; i < 2048; i += 256) {
        sW[i * 2 + 0] = w2s[i] * sc;
        sW[i * 2 + 1] = w2v[i] * sc;
    }
    __syncthreads();

    int warp = tid >> 5, lane = tid & 31;
    int node = blockIdx.x * 8 + warp;

    const float4* ar = (const float4*)(g_acc + (size_t)node * 256);
    ((float4*)srow[warp])[lane]      = ar[lane];
    ((float4*)srow[warp])[lane + 32] = ar[lane + 32];
    __syncwarp();

    unsigned long long acc0 = 0ull, acc1 = 0ull;
#pragma unroll 8
    for (int u = 0; u < 64; u++) {
        float4 q = ((const float4*)srow[warp])[u];
        float2 wsv = ((const float2*)sW)[u * 32 + lane];
        fma2(acc0, pk(q.x, q.y), pk(wsv.x, wsv.y));
        fma2(acc1, pk(q.z, q.w), pk(wsv.y, wsv.y));
    }
    float2 r0 = unpk(acc0), r1 = unpk(acc1);
    float* o = out + (size_t)node * 128;
    o[lane] = r0.x;
    o[32 + lane * 3 + 0] = r0.y;
    o[32 + lane * 3 + 1] = r1.x;
    o[32 + lane * 3 + 2] = r1.y;
}

// ---------------------------------------------------------------------------
extern "C" void kernel_launch(void* const* d_in, const int* in_sizes, int n_in,
                              void* d_out, int out_size) {
    const float* node_input = (const float*)d_in[0];
    const int*   esrc  = (const int*)d_in[2];
    const int*   edst  = (const int*)d_in[3];
    const float* eattr = (const float*)d_in[4];
    const float* escal = (const float*)d_in[5];
    const float* w1s   = (const float*)d_in[6];
    const float* w1v   = (const float*)d_in[7];
    const float* fw1   = (const float*)d_in[8];
    const float* fw2   = (const float*)d_in[9];
    const float* w2s   = (const float*)d_in[10];
    const float* w2v   = (const float*)d_in[11];
    float* out = (float*)d_out;

    static bool attr_set = false;
    if (!attr_set) {
        cudaFuncSetAttribute(edge_kernel,
                             cudaFuncAttributeMaxDynamicSharedMemorySize,
                             EDGE_SMEM_FLOATS * 4);
        attr_set = true;
    }

    prep_zero_kernel<<<(NPAD + 255) / 256, 256>>>();
    hist_kernel<<<(N_EDGES + 255) / 256, 256>>>(edst);
    scan1_kernel<<<40, 1024>>>();
    scatter_kernel<<<(N_EDGES + 255) / 256, 256>>>(esrc, edst,
                                                   (const float4*)eattr,
                                                   (const float4*)escal);
    lin1_kernel<<<N_NODES / 8, 256>>>(node_input, w1s, w1v);
    edge_kernel<<<444, 128, EDGE_SMEM_FLOATS * 4>>>(fw1, fw2);
    lin2_kernel<<<N_NODES / 8, 256>>>(w2s, w2v, out);
}